// round 1
// baseline (speedup 1.0000x reference)
#include <cuda_runtime.h>
#include <math.h>

// ---------------- scratch (__device__ globals; no allocations) ----------------
__device__ float g_x0 [4*16*32*32];     // after 1x1 conv + leaky
__device__ float g_xa [4*4*64*64];      // after pac stage 0
__device__ float g_xb [4*4*128*128];    // after pac stage 1
__device__ float g_xc [4*4*256*256];    // after pac stage 2
__device__ float g_g64 [4*3*64*64];     // resized guides
__device__ float g_g128[4*3*128*128];
__device__ float g_g256[4*3*256*256];

// ---------------- 1x1 conv (384 -> 16) + bias + leaky ----------------
// grid: 128 blocks x 128 threads. Each warp handles 32 pixels for a group of
// 4 output channels; weights staged in shared.
__global__ __launch_bounds__(128) void lin_kernel(
    const float* __restrict__ x,      // (4,384,32,32)
    const float* __restrict__ lw,     // (16,384)
    const float* __restrict__ lb,     // (16)
    float* __restrict__ out)          // (4,16,32,32)
{
    __shared__ float sw[16*384];
    for (int i = threadIdx.x; i < 16*384; i += blockDim.x) sw[i] = lw[i];
    __syncthreads();

    const int og   = threadIdx.x >> 5;          // 0..3 -> output channels og*4..og*4+3
    const int lane = threadIdx.x & 31;
    const int pix  = blockIdx.x * 32 + lane;    // 0..4095
    const int b    = pix >> 10;
    const int hw   = pix & 1023;

    const float* xp = x + b*384*1024 + hw;
    const int o0 = og*4;
    const float* w0p = sw + (o0+0)*384;
    const float* w1p = sw + (o0+1)*384;
    const float* w2p = sw + (o0+2)*384;
    const float* w3p = sw + (o0+3)*384;

    float a0=0.f, a1=0.f, a2=0.f, a3=0.f;
    #pragma unroll 4
    for (int i = 0; i < 384; ++i) {
        float xv = xp[i*1024];
        a0 += w0p[i]*xv;
        a1 += w1p[i]*xv;
        a2 += w2p[i]*xv;
        a3 += w3p[i]*xv;
    }
    a0 += lb[o0+0]; a1 += lb[o0+1]; a2 += lb[o0+2]; a3 += lb[o0+3];
    a0 = (a0 >= 0.f) ? a0 : 0.01f*a0;
    a1 = (a1 >= 0.f) ? a1 : 0.01f*a1;
    a2 = (a2 >= 0.f) ? a2 : 0.01f*a2;
    a3 = (a3 >= 0.f) ? a3 : 0.01f*a3;
    float* op = out + (b*16 + o0)*1024 + hw;
    op[0]      = a0;
    op[1024]   = a1;
    op[2*1024] = a2;
    op[3*1024] = a3;
}

// ---------------- bilinear resize of guide: (4,3,512,512) -> (4,3,OH,OW) ----
__global__ __launch_bounds__(256) void resize_kernel(
    const float* __restrict__ g, float* __restrict__ out, int OH, int OW)
{
    int idx = blockIdx.x*blockDim.x + threadIdx.x;
    int total = 4*3*OH*OW;
    if (idx >= total) return;
    int ow = idx % OW;
    int t  = idx / OW;
    int oh = t % OH;  t /= OH;
    // t = b*3 + c  (plane index)
    const float* gp = g + t*512*512;

    float sh = 512.0f / (float)OH;
    float swc = 512.0f / (float)OW;
    float ch = fmaxf(((float)oh + 0.5f)*sh - 0.5f, 0.0f);
    float cw = fmaxf(((float)ow + 0.5f)*swc - 0.5f, 0.0f);
    int i0 = (int)ch;            int i1 = min(i0+1, 511); float wh = ch - (float)i0;
    int j0 = (int)cw;            int j1 = min(j0+1, 511); float ww = cw - (float)j0;

    float v00 = gp[i0*512 + j0];
    float v01 = gp[i0*512 + j1];
    float v10 = gp[i1*512 + j0];
    float v11 = gp[i1*512 + j1];
    float r0 = v00 + (v01 - v00)*ww;
    float r1 = v10 + (v11 - v10)*ww;
    out[idx] = r0 + (r1 - r0)*wh;
}

// ---------------- PAC conv fused with up2_nearest ----------------
// out[b,o,h,w] = sum_{k in 3x3, in-bounds} exp(-0.5*||g_nb - g_c||^2)
//                * sum_i w[o,i,k] * xprev[b,i,(h+di)/2,(w+dj)/2]
// act: 1 = leaky, 2 = sigmoid
template<int CI, int CO>
__global__ __launch_bounds__(256) void pac_kernel(
    const float* __restrict__ xin,    // (4,CI,H/2,W/2)
    const float* __restrict__ gd,     // (4,3,H,W)
    const float* __restrict__ wt,     // (CO,CI,3,3)
    float* __restrict__ out,          // (4,CO,H,W)
    int H, int W, int act)
{
    __shared__ float sw[CO*CI*9];
    for (int i = threadIdx.x; i < CO*CI*9; i += blockDim.x) sw[i] = wt[i];
    __syncthreads();

    const int HW = H*W;
    int idx = blockIdx.x*blockDim.x + threadIdx.x;
    if (idx >= 4*HW) return;
    const int b  = idx / HW;
    const int hw = idx - b*HW;
    const int h  = hw / W;
    const int w_ = hw - h*W;

    const float* gb = gd + b*3*HW;
    const float gc0 = gb[hw];
    const float gc1 = gb[HW + hw];
    const float gc2 = gb[2*HW + hw];

    const int Hh = H >> 1, Wh = W >> 1;
    const int HWh = Hh*Wh;
    const float* xb = xin + b*CI*HWh;

    float acc[CO];
    #pragma unroll
    for (int o = 0; o < CO; ++o) acc[o] = 0.f;

    #pragma unroll
    for (int k = 0; k < 9; ++k) {
        const int di = k/3 - 1, dj = k%3 - 1;
        const int hh = h + di, ww = w_ + dj;
        if (hh < 0 || hh >= H || ww < 0 || ww >= W) continue;  // zero-padded tap: contributes 0
        const int nhw = hh*W + ww;
        float d0 = gb[nhw]        - gc0;
        float d1 = gb[HW + nhw]   - gc1;
        float d2 = gb[2*HW + nhw] - gc2;
        float kern = expf(-0.5f*(d0*d0 + d1*d1 + d2*d2));

        const int xi = (hh >> 1)*Wh + (ww >> 1);
        float xv[CI];
        #pragma unroll
        for (int i = 0; i < CI; ++i) xv[i] = xb[i*HWh + xi];
        #pragma unroll
        for (int o = 0; o < CO; ++o) {
            float t = 0.f;
            #pragma unroll
            for (int i = 0; i < CI; ++i) t += sw[(o*CI + i)*9 + k] * xv[i];
            acc[o] += kern * t;
        }
    }

    #pragma unroll
    for (int o = 0; o < CO; ++o) {
        float v = acc[o];
        if (act == 1)      v = (v >= 0.f) ? v : 0.01f*v;
        else if (act == 2) v = 1.0f / (1.0f + expf(-v));
        out[(b*CO + o)*HW + hw] = v;
    }
}

// ---------------- launch ----------------
extern "C" void kernel_launch(void* const* d_in, const int* in_sizes, int n_in,
                              void* d_out, int out_size)
{
    const float* x     = (const float*)d_in[0];
    const float* guide = (const float*)d_in[1];
    const float* lin_w = (const float*)d_in[2];
    const float* lin_b = (const float*)d_in[3];
    const float* w0    = (const float*)d_in[4];
    const float* w1    = (const float*)d_in[5];
    const float* w2    = (const float*)d_in[6];
    const float* w3    = (const float*)d_in[7];
    float* out = (float*)d_out;

    float *x0, *xa, *xb, *xc, *gg64, *gg128, *gg256;
    cudaGetSymbolAddress((void**)&x0,    g_x0);
    cudaGetSymbolAddress((void**)&xa,    g_xa);
    cudaGetSymbolAddress((void**)&xb,    g_xb);
    cudaGetSymbolAddress((void**)&xc,    g_xc);
    cudaGetSymbolAddress((void**)&gg64,  g_g64);
    cudaGetSymbolAddress((void**)&gg128, g_g128);
    cudaGetSymbolAddress((void**)&gg256, g_g256);

    // 1x1 conv + leaky: (4,384,32,32) -> (4,16,32,32)
    lin_kernel<<<128, 128>>>(x, lin_w, lin_b, x0);

    // resized guides
    resize_kernel<<<(4*3*64*64   + 255)/256, 256>>>(guide, gg64,  64, 64);
    resize_kernel<<<(4*3*128*128 + 255)/256, 256>>>(guide, gg128, 128, 128);
    resize_kernel<<<(4*3*256*256 + 255)/256, 256>>>(guide, gg256, 256, 256);

    // PAC stages (up2 fused)
    pac_kernel<16,4><<<(4*64*64     + 255)/256, 256>>>(x0, gg64,  w0, xa,  64,  64, 1);
    pac_kernel<4,4> <<<(4*128*128   + 255)/256, 256>>>(xa, gg128, w1, xb, 128, 128, 1);
    pac_kernel<4,4> <<<(4*256*256   + 255)/256, 256>>>(xb, gg256, w2, xc, 256, 256, 1);
    pac_kernel<4,1> <<<(4*512*512   + 255)/256, 256>>>(xc, guide, w3, out, 512, 512, 2);
}

// round 2
// speedup vs baseline: 1.0567x; 1.0567x over previous
#include <cuda_runtime.h>
#include <math.h>

// ---------------- scratch (__device__ globals; no allocations) ----------------
__device__ float g_x0 [4*16*32*32];     // after 1x1 conv + leaky
__device__ float g_xa [4*4*64*64];      // after pac stage 0
__device__ float g_xb [4*4*128*128];    // after pac stage 1
__device__ float g_xc [4*4*256*256];    // after pac stage 2
__device__ float g_g64 [4*3*64*64];     // resized guides
__device__ float g_g128[4*3*128*128];
__device__ float g_g256[4*3*256*256];

// ============================================================================
// PREP kernel: 1x1 conv (384->16) + leaky, fused with all 3 guide resizes.
// Integer-ratio bilinear with half-pixel coords => weights are exactly 0.5:
//   out[oh,ow] = 0.25 * sum of 2x2 block at (f*oh + f/2 - 1, f*ow + f/2 - 1)
// Block dispatch:
//   [0,64)           : lin (4096 pixels, 64 px/block, 4 channel-groups)
//   [64,3136)        : resize f=2 -> 256  (786432 elems)
//   [3136,3904)      : resize f=4 -> 128  (196608 elems)
//   [3904,4096)      : resize f=8 -> 64   ( 49152 elems)
// ============================================================================
__device__ __forceinline__ void resize_level(
    const float* __restrict__ g, float* __restrict__ out, int OH, int f, int idx)
{
    int total = 4*3*OH*OH;
    if (idx >= total) return;
    int ow = idx % OH;
    int t  = idx / OH;
    int oh = t % OH;
    int pl = t / OH;                         // b*3 + c
    const float* gp = g + pl*512*512;
    int i0 = f*oh + (f>>1) - 1;
    int j0 = f*ow + (f>>1) - 1;
    const float* r0 = gp + i0*512 + j0;
    float v = 0.25f*(r0[0] + r0[1] + r0[512] + r0[513]);
    out[idx] = v;
}

__global__ __launch_bounds__(256) void prep_kernel(
    const float* __restrict__ x,      // (4,384,32,32)
    const float* __restrict__ lw,     // (16,384)
    const float* __restrict__ lb,     // (16)
    const float* __restrict__ guide,  // (4,3,512,512)
    float* __restrict__ x0,           // (4,16,32,32)
    float* __restrict__ o256, float* __restrict__ o128, float* __restrict__ o64)
{
    const int bid = blockIdx.x;
    const int tid = threadIdx.x;

    if (bid < 64) {
        // ---- 1x1 conv + leaky ----
        __shared__ float sw[16*384];
        for (int i = tid; i < 16*384; i += 256) sw[i] = lw[i];
        __syncthreads();

        const int pix = bid*64 + (tid & 63);   // 0..4095
        const int b   = pix >> 10;
        const int hw  = pix & 1023;
        const int o0  = (tid >> 6) * 4;        // channel group

        const float* xp  = x + b*384*1024 + hw;
        const float* w0p = sw + (o0+0)*384;
        const float* w1p = sw + (o0+1)*384;
        const float* w2p = sw + (o0+2)*384;
        const float* w3p = sw + (o0+3)*384;

        float a0=0.f, a1=0.f, a2=0.f, a3=0.f;
        #pragma unroll 4
        for (int i = 0; i < 384; ++i) {
            float xv = xp[i*1024];
            a0 += w0p[i]*xv; a1 += w1p[i]*xv; a2 += w2p[i]*xv; a3 += w3p[i]*xv;
        }
        a0 += lb[o0+0]; a1 += lb[o0+1]; a2 += lb[o0+2]; a3 += lb[o0+3];
        a0 = (a0 >= 0.f) ? a0 : 0.01f*a0;
        a1 = (a1 >= 0.f) ? a1 : 0.01f*a1;
        a2 = (a2 >= 0.f) ? a2 : 0.01f*a2;
        a3 = (a3 >= 0.f) ? a3 : 0.01f*a3;
        float* op = x0 + (b*16 + o0)*1024 + hw;
        op[0] = a0; op[1024] = a1; op[2048] = a2; op[3072] = a3;
    } else if (bid < 3136) {
        resize_level(guide, o256, 256, 2, (bid - 64)*256 + tid);
    } else if (bid < 3904) {
        resize_level(guide, o128, 128, 4, (bid - 3136)*256 + tid);
    } else {
        resize_level(guide, o64,   64, 8, (bid - 3904)*256 + tid);
    }
}

// ============================================================================
// PAC stage 0 (CI=16): per-pixel, 64x64 only (negligible cost)
// ============================================================================
template<int CI, int CO>
__global__ __launch_bounds__(256) void pac_kernel(
    const float* __restrict__ xin, const float* __restrict__ gd,
    const float* __restrict__ wt, float* __restrict__ out,
    int H, int W)
{
    __shared__ float sw[CO*CI*9];
    for (int i = threadIdx.x; i < CO*CI*9; i += blockDim.x) sw[i] = wt[i];
    __syncthreads();

    const int HW = H*W;
    int idx = blockIdx.x*blockDim.x + threadIdx.x;
    if (idx >= 4*HW) return;
    const int b  = idx / HW;
    const int hw = idx - b*HW;
    const int h  = hw / W;
    const int w_ = hw - h*W;

    const float* gb = gd + b*3*HW;
    const float gc0 = gb[hw], gc1 = gb[HW + hw], gc2 = gb[2*HW + hw];

    const int Wh = W >> 1;
    const int HWh = (H>>1)*Wh;
    const float* xb = xin + b*CI*HWh;

    float acc[CO];
    #pragma unroll
    for (int o = 0; o < CO; ++o) acc[o] = 0.f;

    #pragma unroll
    for (int k = 0; k < 9; ++k) {
        const int di = k/3 - 1, dj = k%3 - 1;
        const int hh = h + di, ww = w_ + dj;
        if (hh < 0 || hh >= H || ww < 0 || ww >= W) continue;
        const int nhw = hh*W + ww;
        float d0 = gb[nhw]        - gc0;
        float d1 = gb[HW + nhw]   - gc1;
        float d2 = gb[2*HW + nhw] - gc2;
        float kern = __expf(-0.5f*(d0*d0 + d1*d1 + d2*d2));

        const int xi = (hh >> 1)*Wh + (ww >> 1);
        float xv[CI];
        #pragma unroll
        for (int i = 0; i < CI; ++i) xv[i] = xb[i*HWh + xi];
        #pragma unroll
        for (int o = 0; o < CO; ++o) {
            float t = 0.f;
            #pragma unroll
            for (int i = 0; i < CI; ++i) t += sw[(o*CI + i)*9 + k] * xv[i];
            acc[o] += kern * t;
        }
    }

    #pragma unroll
    for (int o = 0; o < CO; ++o) {
        float v = acc[o];
        v = (v >= 0.f) ? v : 0.01f*v;   // stage 0 is always leaky
        out[(b*CO + o)*HW + hw] = v;
    }
}

// ============================================================================
// Blocked PAC (CI=4): one thread computes a 2x2 output block.
// Guide window 4x4x3, x window 3x3x4 (shared across the 4 outputs thanks to
// the fused up2_nearest). ACT: 1 = leaky, 2 = sigmoid.
// ============================================================================
template<int CO, int ACT>
__global__ __launch_bounds__(256) void pac2_kernel(
    const float* __restrict__ xin,    // (4,4,H/2,W/2)
    const float* __restrict__ gd,     // (4,3,H,W)
    const float* __restrict__ wt,     // (CO,4,3,3)
    float* __restrict__ out,          // (4,CO,H,W)
    int H, int W)
{
    __shared__ float sw[CO*4*9];
    for (int i = threadIdx.x; i < CO*4*9; i += blockDim.x) sw[i] = wt[i];
    __syncthreads();

    const int H2 = H >> 1, W2 = W >> 1;
    const int HW2 = H2*W2;
    int idx = blockIdx.x*blockDim.x + threadIdx.x;
    if (idx >= 4*HW2) return;
    const int b   = idx / HW2;
    const int hw2 = idx - b*HW2;
    const int h2  = hw2 / W2;
    const int w2  = hw2 - h2*W2;
    const int h = h2 << 1, w = w2 << 1;
    const int HW = H*W;

    // ---- guide window: rows h-1..h+2, cols w-1..w+2, 3 channels ----
    const float* gb = gd + b*3*HW;
    float gwin[3][16];
    #pragma unroll
    for (int rr = 0; rr < 4; ++rr) {
        const int r = h - 1 + rr;
        const bool rok = (r >= 0) && (r < H);
        #pragma unroll
        for (int cc = 0; cc < 4; ++cc) {
            const int c = w - 1 + cc;
            const bool ok = rok && (c >= 0) && (c < W);
            const int off = r*W + c;
            gwin[0][rr*4+cc] = ok ? gb[off]        : 0.f;
            gwin[1][rr*4+cc] = ok ? gb[HW + off]   : 0.f;
            gwin[2][rr*4+cc] = ok ? gb[2*HW + off] : 0.f;
        }
    }

    // ---- x window: half-res rows h2-1..h2+1, cols w2-1..w2+1, 4 channels ----
    const float* xb = xin + b*4*HW2;
    float xwin[4][9];
    #pragma unroll
    for (int rr = 0; rr < 3; ++rr) {
        const int r = h2 - 1 + rr;
        const bool rok = (r >= 0) && (r < H2);
        #pragma unroll
        for (int cc = 0; cc < 3; ++cc) {
            const int c = w2 - 1 + cc;
            const bool ok = rok && (c >= 0) && (c < W2);
            const int off = r*W2 + c;
            #pragma unroll
            for (int i = 0; i < 4; ++i)
                xwin[i][rr*3+cc] = ok ? xb[i*HW2 + off] : 0.f;
        }
    }

    // ---- compute 2x2 outputs ----
    #pragma unroll
    for (int r = 0; r < 2; ++r) {
        #pragma unroll
        for (int c = 0; c < 2; ++c) {
            const float gc0 = gwin[0][(r+1)*4 + (c+1)];
            const float gc1 = gwin[1][(r+1)*4 + (c+1)];
            const float gc2 = gwin[2][(r+1)*4 + (c+1)];
            float acc[CO];
            #pragma unroll
            for (int o = 0; o < CO; ++o) acc[o] = 0.f;

            #pragma unroll
            for (int k = 0; k < 9; ++k) {
                const int t = r + k/3 - 1;       // row offset within window - 1
                const int u = c + k%3 - 1;
                const bool ok = (h + t >= 0) && (h + t < H) && (w + u >= 0) && (w + u < W);
                const int gi = (t+1)*4 + (u+1);
                float d0 = gwin[0][gi] - gc0;
                float d1 = gwin[1][gi] - gc1;
                float d2 = gwin[2][gi] - gc2;
                float kern = ok ? __expf(-0.5f*(d0*d0 + d1*d1 + d2*d2)) : 0.f;
                const int xo = ((t>>1)+1)*3 + ((u>>1)+1);   // compile-time after unroll
                #pragma unroll
                for (int o = 0; o < CO; ++o) {
                    float s = 0.f;
                    #pragma unroll
                    for (int i = 0; i < 4; ++i) s += sw[(o*4 + i)*9 + k] * xwin[i][xo];
                    acc[o] += kern * s;
                }
            }

            const int ohw = (h+r)*W + (w+c);
            #pragma unroll
            for (int o = 0; o < CO; ++o) {
                float v = acc[o];
                if (ACT == 1)      v = (v >= 0.f) ? v : 0.01f*v;
                else               v = 1.0f / (1.0f + __expf(-v));
                out[(b*CO + o)*HW + ohw] = v;
            }
        }
    }
}

// ---------------- launch ----------------
extern "C" void kernel_launch(void* const* d_in, const int* in_sizes, int n_in,
                              void* d_out, int out_size)
{
    const float* x     = (const float*)d_in[0];
    const float* guide = (const float*)d_in[1];
    const float* lin_w = (const float*)d_in[2];
    const float* lin_b = (const float*)d_in[3];
    const float* w0    = (const float*)d_in[4];
    const float* w1    = (const float*)d_in[5];
    const float* w2    = (const float*)d_in[6];
    const float* w3    = (const float*)d_in[7];
    float* out = (float*)d_out;

    float *x0, *xa, *xb, *xc, *gg64, *gg128, *gg256;
    cudaGetSymbolAddress((void**)&x0,    g_x0);
    cudaGetSymbolAddress((void**)&xa,    g_xa);
    cudaGetSymbolAddress((void**)&xb,    g_xb);
    cudaGetSymbolAddress((void**)&xc,    g_xc);
    cudaGetSymbolAddress((void**)&gg64,  g_g64);
    cudaGetSymbolAddress((void**)&gg128, g_g128);
    cudaGetSymbolAddress((void**)&gg256, g_g256);

    // prep: 1x1 conv + all resizes (64 + 3072 + 768 + 192 = 4096 blocks)
    prep_kernel<<<4096, 256>>>(x, lin_w, lin_b, guide, x0, gg256, gg128, gg64);

    // PAC stages (up2 fused)
    pac_kernel<16,4><<<(4*64*64 + 255)/256, 256>>>(x0, gg64, w0, xa, 64, 64);
    pac2_kernel<4,1><<<(4*64*64    + 255)/256, 256>>>(xa, gg128, w1, xb, 128, 128);
    pac2_kernel<4,1><<<(4*128*128  + 255)/256, 256>>>(xb, gg256, w2, xc, 256, 256);
    pac2_kernel<1,2><<<(4*256*256  + 255)/256, 256>>>(xc, guide, w3, out, 512, 512);
}

// round 3
// speedup vs baseline: 1.0596x; 1.0028x over previous
#include <cuda_runtime.h>
#include <math.h>

// ---------------- scratch (__device__ globals; no allocations) ----------------
__device__ float g_x0 [4*16*32*32];
__device__ float g_xa [4*4*64*64];
__device__ float g_xb [4*4*128*128];
__device__ float g_xc [4*4*256*256];
__device__ float g_g64 [4*3*64*64];
__device__ float g_g128[4*3*128*128];
__device__ float g_g256[4*3*256*256];

// ============================================================================
// PREP: 1x1 conv (384->16)+leaky fused with all 3 guide resizes.
// Integer-ratio bilinear, half-pixel => exact 0.25 * 2x2 box at fixed offset.
// ============================================================================
__device__ __forceinline__ void resize_level(
    const float* __restrict__ g, float* __restrict__ out, int OH, int f, int idx)
{
    if (idx >= 4*3*OH*OH) return;
    int ow = idx % OH;
    int t  = idx / OH;
    int oh = t % OH;
    int pl = t / OH;
    const float* gp = g + pl*512*512;
    const float* r0 = gp + (f*oh + (f>>1) - 1)*512 + (f*ow + (f>>1) - 1);
    out[idx] = 0.25f*(r0[0] + r0[1] + r0[512] + r0[513]);
}

__global__ __launch_bounds__(256) void prep_kernel(
    const float* __restrict__ x, const float* __restrict__ lw,
    const float* __restrict__ lb, const float* __restrict__ guide,
    float* __restrict__ x0,
    float* __restrict__ o256, float* __restrict__ o128, float* __restrict__ o64)
{
    const int bid = blockIdx.x;
    const int tid = threadIdx.x;

    if (bid < 64) {
        __shared__ float sw[16*384];
        for (int i = tid; i < 16*384; i += 256) sw[i] = lw[i];
        __syncthreads();
        const int pix = bid*64 + (tid & 63);
        const int b   = pix >> 10;
        const int hw  = pix & 1023;
        const int o0  = (tid >> 6) * 4;
        const float* xp  = x + b*384*1024 + hw;
        const float* w0p = sw + (o0+0)*384;
        const float* w1p = sw + (o0+1)*384;
        const float* w2p = sw + (o0+2)*384;
        const float* w3p = sw + (o0+3)*384;
        float a0=0.f, a1=0.f, a2=0.f, a3=0.f;
        #pragma unroll 4
        for (int i = 0; i < 384; ++i) {
            float xv = xp[i*1024];
            a0 += w0p[i]*xv; a1 += w1p[i]*xv; a2 += w2p[i]*xv; a3 += w3p[i]*xv;
        }
        a0 += lb[o0+0]; a1 += lb[o0+1]; a2 += lb[o0+2]; a3 += lb[o0+3];
        a0 = (a0 >= 0.f) ? a0 : 0.01f*a0;
        a1 = (a1 >= 0.f) ? a1 : 0.01f*a1;
        a2 = (a2 >= 0.f) ? a2 : 0.01f*a2;
        a3 = (a3 >= 0.f) ? a3 : 0.01f*a3;
        float* op = x0 + (b*16 + o0)*1024 + hw;
        op[0] = a0; op[1024] = a1; op[2048] = a2; op[3072] = a3;
    } else if (bid < 3136) {
        resize_level(guide, o256, 256, 2, (bid - 64)*256 + tid);
    } else if (bid < 3904) {
        resize_level(guide, o128, 128, 4, (bid - 3136)*256 + tid);
    } else {
        resize_level(guide, o64,   64, 8, (bid - 3904)*256 + tid);
    }
}

// ============================================================================
// Tiled PAC conv fused with up2_nearest.
// Block = 32x8 output pixels. Guide tile (3 x 10x34) and half-res x tile
// (CI x 6x18) staged in shared memory. For CO==1, weights live in registers.
// ACT: 1 = leaky, 2 = sigmoid.
// ============================================================================
#define TW 32
#define TH 8
#define GP (TW+2)          // 34
#define GTILE ((TH+2)*GP)  // 340
#define XP (TW/2+2)        // 18
#define XTILE ((TH/2+2)*XP)// 108

template<int CI, int CO, int ACT>
__global__ __launch_bounds__(256) void pac_tile(
    const float* __restrict__ xin,   // (4,CI,H/2,W/2)
    const float* __restrict__ gd,    // (4,3,H,W)
    const float* __restrict__ wt,    // (CO,CI,3,3)
    float* __restrict__ out,         // (4,CO,H,W)
    int H, int W)
{
    __shared__ float sg[3*GTILE];
    __shared__ float sx[CI*XTILE];
    __shared__ float swt[CO*CI*9];

    const int tid = threadIdx.x;
    const int b   = blockIdx.z;
    const int h0  = blockIdx.y * TH;
    const int w0  = blockIdx.x * TW;
    const int HW  = H*W;
    const int H2 = H >> 1, W2 = W >> 1, HW2 = H2*W2;

    // ---- stage guide tile ----
    const float* gb = gd + b*3*HW;
    for (int i = tid; i < 3*GTILE; i += 256) {
        int c = i / GTILE, j = i - c*GTILE;
        int r = j / GP,    q = j - r*GP;
        int gh = h0 - 1 + r, gw = w0 - 1 + q;
        bool ok = (gh >= 0) & (gh < H) & (gw >= 0) & (gw < W);
        sg[i] = ok ? gb[c*HW + gh*W + gw] : 0.f;
    }
    // ---- stage x tile (half-res) ----
    const float* xb = xin + b*CI*HW2;
    for (int i = tid; i < CI*XTILE; i += 256) {
        int c = i / XTILE, j = i - c*XTILE;
        int r = j / XP,    q = j - r*XP;
        int xh = (h0>>1) - 1 + r, xw = (w0>>1) - 1 + q;
        bool ok = (xh >= 0) & (xh < H2) & (xw >= 0) & (xw < W2);
        sx[i] = ok ? xb[c*HW2 + xh*W2 + xw] : 0.f;
    }
    // ---- weights ----
    float wr[CO == 1 ? CI*9 : 1];
    if (CO == 1) {
        #pragma unroll
        for (int i = 0; i < CI*9; ++i) wr[i] = __ldg(wt + i);
    } else {
        for (int i = tid; i < CO*CI*9; i += 256) swt[i] = wt[i];
    }
    __syncthreads();

    const int ty = tid >> 5, tx = tid & 31;
    const int h = h0 + ty, w = w0 + tx;
    const int gi0 = (ty+1)*GP + (tx+1);
    const float gc0 = sg[gi0];
    const float gc1 = sg[GTILE + gi0];
    const float gc2 = sg[2*GTILE + gi0];

    float acc[CO];
    #pragma unroll
    for (int o = 0; o < CO; ++o) acc[o] = 0.f;

    #pragma unroll
    for (int k = 0; k < 9; ++k) {
        const int di = k/3 - 1, dj = k%3 - 1;
        const bool ok = (h+di >= 0) & (h+di < H) & (w+dj >= 0) & (w+dj < W);
        const int gi = gi0 + di*GP + dj;
        float d0 = sg[gi]           - gc0;
        float d1 = sg[GTILE + gi]   - gc1;
        float d2 = sg[2*GTILE + gi] - gc2;
        float kern = ok ? __expf(-0.5f*(d0*d0 + d1*d1 + d2*d2)) : 0.f;

        const int xo = (((ty+di)>>1)+1)*XP + (((tx+dj)>>1)+1);
        float xv[CI];
        #pragma unroll
        for (int i = 0; i < CI; ++i) xv[i] = sx[i*XTILE + xo];
        #pragma unroll
        for (int o = 0; o < CO; ++o) {
            float s = 0.f;
            #pragma unroll
            for (int i = 0; i < CI; ++i) {
                float wv = (CO == 1) ? wr[i*9 + k] : swt[(o*CI + i)*9 + k];
                s += wv * xv[i];
            }
            acc[o] += kern * s;
        }
    }

    #pragma unroll
    for (int o = 0; o < CO; ++o) {
        float v = acc[o];
        if (ACT == 1) v = (v >= 0.f) ? v : 0.01f*v;
        else          v = 1.0f / (1.0f + __expf(-v));
        out[(b*CO + o)*HW + h*W + w] = v;
    }
}

// ---------------- launch ----------------
extern "C" void kernel_launch(void* const* d_in, const int* in_sizes, int n_in,
                              void* d_out, int out_size)
{
    const float* x     = (const float*)d_in[0];
    const float* guide = (const float*)d_in[1];
    const float* lin_w = (const float*)d_in[2];
    const float* lin_b = (const float*)d_in[3];
    const float* w0    = (const float*)d_in[4];
    const float* w1    = (const float*)d_in[5];
    const float* w2    = (const float*)d_in[6];
    const float* w3    = (const float*)d_in[7];
    float* out = (float*)d_out;

    float *x0, *xa, *xb, *xc, *gg64, *gg128, *gg256;
    cudaGetSymbolAddress((void**)&x0,    g_x0);
    cudaGetSymbolAddress((void**)&xa,    g_xa);
    cudaGetSymbolAddress((void**)&xb,    g_xb);
    cudaGetSymbolAddress((void**)&xc,    g_xc);
    cudaGetSymbolAddress((void**)&gg64,  g_g64);
    cudaGetSymbolAddress((void**)&gg128, g_g128);
    cudaGetSymbolAddress((void**)&gg256, g_g256);

    prep_kernel<<<4096, 256>>>(x, lin_w, lin_b, guide, x0, gg256, gg128, gg64);

    pac_tile<16,4,1><<<dim3( 2,  8, 4), 256>>>(x0, gg64,  w0, xa,  64,  64);
    pac_tile< 4,4,1><<<dim3( 4, 16, 4), 256>>>(xa, gg128, w1, xb, 128, 128);
    pac_tile< 4,4,1><<<dim3( 8, 32, 4), 256>>>(xb, gg256, w2, xc, 256, 256);
    pac_tile< 4,1,2><<<dim3(16, 64, 4), 256>>>(xc, guide, w3, out, 512, 512);
}

// round 4
// speedup vs baseline: 1.3694x; 1.2923x over previous
#include <cuda_runtime.h>
#include <math.h>

// ---------------- scratch (__device__ globals; no allocations) ----------------
__device__ float g_x0 [4*16*32*32];
__device__ float g_xa [4*4*64*64];
__device__ float g_xb [4*4*128*128];
__device__ float g_xc [4*4*256*256];
__device__ float g_g64 [4*3*64*64];
__device__ float g_g128[4*3*128*128];
__device__ float g_g256[4*3*256*256];

// ============================================================================
// PREP: 1x1 conv (384->16)+leaky fused with all 3 guide resizes.
// Half-pixel integer-ratio bilinear => exact 0.25 * 2x2 box.
// f=2 is an aligned 2x2 avg-pool -> fully vectorized (4 out/thread).
// Block dispatch: [0,64) lin | [64,832) f=2 vec | [832,1600) f=4 | [1600,1792) f=8
// ============================================================================
__device__ __forceinline__ void resize_scalar(
    const float* __restrict__ g, float* __restrict__ out, int OH, int f, int idx)
{
    if (idx >= 4*3*OH*OH) return;
    int ow = idx % OH;
    int t  = idx / OH;
    int oh = t % OH;
    int pl = t / OH;
    const float* gp = g + pl*512*512;
    const float* r0 = gp + (f*oh + (f>>1) - 1)*512 + (f*ow + (f>>1) - 1);
    out[idx] = 0.25f*(r0[0] + r0[1] + r0[512] + r0[513]);
}

__global__ __launch_bounds__(256) void prep_kernel(
    const float* __restrict__ x, const float* __restrict__ lw,
    const float* __restrict__ lb, const float* __restrict__ guide,
    float* __restrict__ x0,
    float* __restrict__ o256, float* __restrict__ o128, float* __restrict__ o64)
{
    const int bid = blockIdx.x;
    const int tid = threadIdx.x;

    if (bid < 64) {
        __shared__ float sw[16*384];
        for (int i = tid; i < 16*384; i += 256) sw[i] = lw[i];
        __syncthreads();
        const int pix = bid*64 + (tid & 63);
        const int b   = pix >> 10;
        const int hw  = pix & 1023;
        const int o0  = (tid >> 6) * 4;
        const float* xp  = x + b*384*1024 + hw;
        const float* w0p = sw + (o0+0)*384;
        const float* w1p = sw + (o0+1)*384;
        const float* w2p = sw + (o0+2)*384;
        const float* w3p = sw + (o0+3)*384;
        float a0=0.f, a1=0.f, a2=0.f, a3=0.f;
        #pragma unroll 4
        for (int i = 0; i < 384; ++i) {
            float xv = xp[i*1024];
            a0 += w0p[i]*xv; a1 += w1p[i]*xv; a2 += w2p[i]*xv; a3 += w3p[i]*xv;
        }
        a0 += lb[o0+0]; a1 += lb[o0+1]; a2 += lb[o0+2]; a3 += lb[o0+3];
        a0 = (a0 >= 0.f) ? a0 : 0.01f*a0;
        a1 = (a1 >= 0.f) ? a1 : 0.01f*a1;
        a2 = (a2 >= 0.f) ? a2 : 0.01f*a2;
        a3 = (a3 >= 0.f) ? a3 : 0.01f*a3;
        float* op = x0 + (b*16 + o0)*1024 + hw;
        op[0] = a0; op[1024] = a1; op[2048] = a2; op[3072] = a3;
    } else if (bid < 832) {
        // f=2: (pl,oh,ow4) over 4*3*256*64 threads; 4 outputs each
        int idx = (bid - 64)*256 + tid;               // < 196608
        int ow4 = idx & 63;
        int t   = idx >> 6;
        int oh  = t & 255;
        int pl  = t >> 8;
        const float* gp = guide + pl*512*512 + (2*oh)*512 + ow4*8;
        float4 a = ((const float4*)gp)[0];
        float4 b4 = ((const float4*)gp)[1];
        float4 c = ((const float4*)(gp + 512))[0];
        float4 d = ((const float4*)(gp + 512))[1];
        float4 r;
        r.x = 0.25f*(a.x + a.y + c.x + c.y);
        r.y = 0.25f*(a.z + a.w + c.z + c.w);
        r.z = 0.25f*(b4.x + b4.y + d.x + d.y);
        r.w = 0.25f*(b4.z + b4.w + d.z + d.w);
        ((float4*)o256)[idx] = r;
    } else if (bid < 1600) {
        resize_scalar(guide, o128, 128, 4, (bid - 832)*256 + tid);
    } else {
        resize_scalar(guide, o64,   64, 8, (bid - 1600)*256 + tid);
    }
}

// ============================================================================
// Tiled PAC conv fused with up2_nearest. float4 smem tiles, sentinel OOB.
// Block = 32x8 outputs. ACT: 1 = leaky, 2 = sigmoid.
// ============================================================================
#define TW 32
#define TH 8
#define GP (TW+2)            // 34
#define GTILE ((TH+2)*GP)    // 340
#define XP (TW/2+2)          // 18
#define XTILE ((TH/2+2)*XP)  // 108

template<int CI, int CO, int ACT>
__global__ __launch_bounds__(256) void pac_tile(
    const float* __restrict__ xin,   // (4,CI,H/2,W/2)
    const float* __restrict__ gd,    // (4,3,H,W)
    const float* __restrict__ wt,    // (CO,CI,3,3)
    float* __restrict__ out,         // (4,CO,H,W)
    int H, int W)
{
    constexpr int NC4 = CI/4;
    __shared__ float4 sg[GTILE];             // guide: {g0,g1,g2,_} per pixel
    __shared__ float4 sx[XTILE*NC4];         // x: NC4 float4 per half-res pixel
    __shared__ float4 swt[9*CO*NC4];         // weights k-major: [k][o][c4]

    const int tid = threadIdx.x;
    const int b   = blockIdx.z;
    const int h0  = blockIdx.y * TH;
    const int w0  = blockIdx.x * TW;
    const int HW  = H*W;
    const int H2 = H >> 1, W2 = W >> 1, HW2 = H2*W2;

    // ---- stage guide tile (sentinel 1e19 outside image -> kern == 0) ----
    const float* gb = gd + b*3*HW;
    for (int i = tid; i < GTILE; i += 256) {
        int r = i / GP, q = i - r*GP;
        int gh = h0 - 1 + r, gw = w0 - 1 + q;
        float4 v;
        if ((gh >= 0) & (gh < H) & (gw >= 0) & (gw < W)) {
            int off = gh*W + gw;
            v.x = gb[off]; v.y = gb[HW + off]; v.z = gb[2*HW + off];
        } else {
            v.x = v.y = v.z = 1e19f;
        }
        v.w = 0.f;
        sg[i] = v;
    }
    // ---- stage x tile (half-res, zero halo) ----
    const float* xb = xin + b*CI*HW2;
    for (int i = tid; i < XTILE*NC4; i += 256) {
        int pos = i / NC4, c4 = i - pos*NC4;
        int r = pos / XP, q = pos - r*XP;
        int xh = (h0>>1) - 1 + r, xw = (w0>>1) - 1 + q;
        float4 v = make_float4(0.f, 0.f, 0.f, 0.f);
        if ((xh >= 0) & (xh < H2) & (xw >= 0) & (xw < W2)) {
            int off = xh*W2 + xw;
            const float* p = xb + (c4*4)*HW2 + off;
            v.x = p[0]; v.y = p[HW2]; v.z = p[2*HW2]; v.w = p[3*HW2];
        }
        sx[i] = v;
    }
    // ---- stage weights k-major: swt[(k*CO + o)*NC4 + c4].j = wt[(o, c4*4+j, k)] ----
    for (int i = tid; i < 9*CO*NC4; i += 256) {
        int c4 = i % NC4;
        int t2 = i / NC4;
        int o  = t2 % CO;
        int k  = t2 / CO;
        float4 v;
        v.x = wt[(o*CI + c4*4 + 0)*9 + k];
        v.y = wt[(o*CI + c4*4 + 1)*9 + k];
        v.z = wt[(o*CI + c4*4 + 2)*9 + k];
        v.w = wt[(o*CI + c4*4 + 3)*9 + k];
        swt[i] = v;
    }
    __syncthreads();

    const int ty = tid >> 5, tx = tid & 31;
    const int h = h0 + ty, w = w0 + tx;
    const int gi0 = (ty+1)*GP + (tx+1);
    const float4 gc = sg[gi0];

    float acc[CO];
    #pragma unroll
    for (int o = 0; o < CO; ++o) acc[o] = 0.f;

    #pragma unroll
    for (int k = 0; k < 9; ++k) {
        const int di = k/3 - 1, dj = k%3 - 1;
        float4 g4 = sg[gi0 + di*GP + dj];
        float d0 = g4.x - gc.x, d1 = g4.y - gc.y, d2 = g4.z - gc.z;
        float kern = __expf(-0.5f*(d0*d0 + d1*d1 + d2*d2));

        const int xo = ((((ty+di)>>1)+1)*XP + (((tx+dj)>>1)+1)) * NC4;
        #pragma unroll
        for (int o = 0; o < CO; ++o) {
            float s = 0.f;
            #pragma unroll
            for (int c4 = 0; c4 < NC4; ++c4) {
                float4 xv = sx[xo + c4];
                float4 wv = swt[(k*CO + o)*NC4 + c4];
                s += wv.x*xv.x + wv.y*xv.y + wv.z*xv.z + wv.w*xv.w;
            }
            acc[o] += kern * s;
        }
    }

    #pragma unroll
    for (int o = 0; o < CO; ++o) {
        float v = acc[o];
        if (ACT == 1) v = (v >= 0.f) ? v : 0.01f*v;
        else          v = 1.0f / (1.0f + __expf(-v));
        out[(b*CO + o)*HW + h*W + w] = v;
    }
}

// ---------------- launch ----------------
extern "C" void kernel_launch(void* const* d_in, const int* in_sizes, int n_in,
                              void* d_out, int out_size)
{
    const float* x     = (const float*)d_in[0];
    const float* guide = (const float*)d_in[1];
    const float* lin_w = (const float*)d_in[2];
    const float* lin_b = (const float*)d_in[3];
    const float* w0    = (const float*)d_in[4];
    const float* w1    = (const float*)d_in[5];
    const float* w2    = (const float*)d_in[6];
    const float* w3    = (const float*)d_in[7];
    float* out = (float*)d_out;

    float *x0, *xa, *xb, *xc, *gg64, *gg128, *gg256;
    cudaGetSymbolAddress((void**)&x0,    g_x0);
    cudaGetSymbolAddress((void**)&xa,    g_xa);
    cudaGetSymbolAddress((void**)&xb,    g_xb);
    cudaGetSymbolAddress((void**)&xc,    g_xc);
    cudaGetSymbolAddress((void**)&gg64,  g_g64);
    cudaGetSymbolAddress((void**)&gg128, g_g128);
    cudaGetSymbolAddress((void**)&gg256, g_g256);

    // prep: 64 lin + 768 f2-vec + 768 f4 + 192 f8 = 1792 blocks
    prep_kernel<<<1792, 256>>>(x, lin_w, lin_b, guide, x0, gg256, gg128, gg64);

    pac_tile<16,4,1><<<dim3( 2,  8, 4), 256>>>(x0, gg64,  w0, xa,  64,  64);
    pac_tile< 4,4,1><<<dim3( 4, 16, 4), 256>>>(xa, gg128, w1, xb, 128, 128);
    pac_tile< 4,4,1><<<dim3( 8, 32, 4), 256>>>(xb, gg256, w2, xc, 256, 256);
    pac_tile< 4,1,2><<<dim3(16, 64, 4), 256>>>(xc, guide, w3, out, 512, 512);
}